// round 16
// baseline (speedup 1.0000x reference)
#include <cuda_runtime.h>
#include <cuda_bf16.h>
#include <math.h>
#include <stdint.h>

#define BB   4
#define TT   16
#define NN   2048
#define DD   64
#define EPSF 1e-4f
#define IEPS 1e4f
#define BTN  (BB*TT*NN)   // 131072 = 2^17
#define MARGIN 0.25f

typedef unsigned long long u64;

// static device scratch (no allocations)
__device__ float  g_sqx[BTN];
__device__ float  g_sqy[BTN];
__device__ double g_lossPart[2][256];
// bf16 hi-only storage: per row 64 bf16
__device__ __nv_bfloat16 g_xh[(size_t)BTN * 64];
__device__ __nv_bfloat16 g_yh[(size_t)BTN * 64];

__device__ __forceinline__ uint32_t smem_u32(const void* p) {
    uint32_t a;
    asm("{ .reg .u64 t; cvta.to.shared.u64 t, %1; cvt.u32.u64 %0, t; }"
        : "=r"(a) : "l"(p));
    return a;
}
__device__ __forceinline__ void ldsm4(uint32_t* r, uint32_t addr) {
    asm volatile("ldmatrix.sync.aligned.m8n8.x4.shared.b16 {%0,%1,%2,%3}, [%4];"
        : "=r"(r[0]), "=r"(r[1]), "=r"(r[2]), "=r"(r[3]) : "r"(addr));
}
__device__ __forceinline__ void mma16816(float* d, const uint32_t* a,
                                         const uint32_t* b) {
    asm volatile(
        "mma.sync.aligned.m16n8k16.row.col.f32.bf16.bf16.f32 "
        "{%0,%1,%2,%3}, {%4,%5,%6,%7}, {%8,%9}, {%0,%1,%2,%3};"
        : "+f"(d[0]), "+f"(d[1]), "+f"(d[2]), "+f"(d[3])
        : "r"(a[0]), "r"(a[1]), "r"(a[2]), "r"(a[3]), "r"(b[0]), "r"(b[1]));
}
__device__ __forceinline__ void cpasync16(uint32_t sm, const void* g) {
    asm volatile("cp.async.cg.shared.global [%0], [%1], 16;"
                 :: "r"(sm), "l"(g));
}
#define CP_COMMIT() asm volatile("cp.async.commit_group;" ::: "memory")

// ---------------- small kernels ----------------
__global__ void split_kernel(const float* __restrict__ x, const float* __restrict__ y) {
    int id = blockIdx.x * 256 + threadIdx.x;       // 0 .. 2*BTN*16-1
    int kind = id >> 21;                            // BTN*16 = 2^21
    int r = id & ((1 << 21) - 1);
    int row = r >> 4, c4 = (r & 15) << 2;
    const float* src = (kind ? y : x) + (size_t)row * DD + c4;
    float4 v = *(const float4*)src;
    union { __nv_bfloat16 h[4]; u64 v; } H;
    H.h[0] = __float2bfloat16(v.x);
    H.h[1] = __float2bfloat16(v.y);
    H.h[2] = __float2bfloat16(v.z);
    H.h[3] = __float2bfloat16(v.w);
    *(u64*)((kind ? g_yh : g_xh) + (size_t)row * 64 + c4) = H.v;
}

__global__ void norms_kernel(const float* __restrict__ x, const float* __restrict__ y) {
    int id = blockIdx.x * 256 + threadIdx.x;
    int kind = id >> 17;
    int r = id & (BTN - 1);
    const float4* v = (const float4*)((kind ? y : x) + (size_t)r * DD);
    float s = 0.f;
#pragma unroll
    for (int k = 0; k < 16; k++) {
        float4 q = v[k];
        s += q.x * q.x + q.y * q.y + q.z * q.z + q.w * q.w;
    }
    (kind ? g_sqy : g_sqx)[r] = s;
}

__global__ void init_kernel(float* __restrict__ out) {
    int id = blockIdx.x * blockDim.x + threadIdx.x;   // 0..8191
    if (id < 4) out[id * TT] = 0.f;
    int b = id >> 11, i = id & 2047;
    out[64 + (b * TT) * NN + i] = 0.f;
    out[64 + BTN + (b * TT) * NN + i] = 0.f;
}

// ---------------- main kernel: hi-only screening GEMM + exact rescoring ----
// grid = 256: dir(2) x b(4) x rowblock(32). Block tile 64 rows x 2048 cols.
// 2 CTAs/SM. Warp tile 16x64. hi-only bf16 MMA produces p~ (err << 0.25);
// candidate cols (p~ > runmax-0.25) go to per-(thread,row-half) SMEM rings;
// final pass recomputes exact fp32 p for candidates and takes exact softmin.
// SMEM: B ring 3x16K = 0..48K | Ah 48K..56K | Af(fp32 A rows) 56K..72K |
//       Cs 72K..80K | RING 80K..98K | dsm 98K..100K
#define OFF_AH   49152
#define OFF_AF   57344
#define OFF_CSV  73728
#define OFF_RING 81920
#define OFF_DSM  100352
#define SMEM_TOT 102400

__global__ __launch_bounds__(256, 2)
void main_kernel(int step,
                 const float* __restrict__ x, const float* __restrict__ y,
                 const float* __restrict__ loga, const float* __restrict__ logb,
                 float* __restrict__ out) {
    extern __shared__ char smem[];
    const uint32_t sb = smem_u32(smem);
    float*    Cs   = (float*)(smem + OFF_CSV);
    uint32_t* ring = (uint32_t*)(smem + OFF_RING);
    double*   dsm  = (double*)(smem + OFF_DSM);

    const int tid = threadIdx.x;
    const int bid = blockIdx.x;
    const int dir = bid >> 7;
    const int b   = (bid >> 5) & 3;
    const int rb  = bid & 31;
    const int r0  = rb * 64;
    const int lane = tid & 31, wid = tid >> 5;
    const int warp_r = wid >> 1, warp_c = wid & 1;   // 4 x 2 warps, tile 16x64

    const size_t curBase  = (size_t)(b * TT + step) * NN;
    const size_t prevBase = curBase - NN;

    const __nv_bfloat16* Ah_src = (dir == 0 ? g_xh : g_yh) + (curBase + r0) * 64;
    const __nv_bfloat16* Bh_src = (dir == 0 ? g_yh : g_xh) + prevBase * 64;
    const float* Afp_src = (dir == 0 ? x : y) + (curBase + r0) * DD;
    const float* Bfp     = (dir == 0 ? y : x) + prevBase * DD;
    const float* prevPot = out + 64 + (dir == 0 ? BTN : 0);
    const float* lvec    = (dir == 0 ? logb : loga);
    const float* sqPrev  = (dir == 0 ? g_sqy : g_sqx);
    const float* sqCur   = (dir == 0 ? g_sqx : g_sqy);

    // --- prologue loads ---
    // Ah (64 rows x 8 chunks): 2/thread
#pragma unroll
    for (int j = 0; j < 2; j++) {
        int idx = tid + 256 * j;
        int row = idx >> 3, ch = idx & 7;
        cpasync16(sb + OFF_AH + (uint32_t)(row * 128 + ((ch ^ (row & 7)) << 4)),
                  Ah_src + (size_t)row * 64 + ch * 8);
    }
    // Af fp32 rows (64 x 16 chunks): 4/thread, plain layout
#pragma unroll
    for (int j = 0; j < 4; j++) {
        int idx = tid + 256 * j;
        int row = idx >> 4, ch = idx & 15;
        cpasync16(sb + OFF_AF + (uint32_t)(row * 256 + ch * 16),
                  Afp_src + (size_t)row * 64 + ch * 4);
    }
    // B tile 0 (128 rows x 8 chunks): 4/thread
#pragma unroll
    for (int j = 0; j < 4; j++) {
        int idx = tid + 256 * j;
        int row = idx >> 3, ch = idx & 7;
        cpasync16(sb + (uint32_t)(row * 128 + ((ch ^ (row & 7)) << 4)),
                  Bh_src + (size_t)row * 64 + ch * 8);
    }
    CP_COMMIT();
    // B tile 1
#pragma unroll
    for (int j = 0; j < 4; j++) {
        int idx = tid + 256 * j;
        int row = idx >> 3, ch = idx & 7;
        cpasync16(sb + 16384 + (uint32_t)(row * 128 + ((ch ^ (row & 7)) << 4)),
                  Bh_src + (size_t)(128 + row) * 64 + ch * 8);
    }
    CP_COMMIT();
    // c vector: c = pot_prev + EPS*log(ab) - ||prev||^2
#pragma unroll
    for (int j = 0; j < 8; j++) {
        int col = tid + 256 * j;
        Cs[col] = prevPot[prevBase + col] + EPSF * lvec[prevBase + col]
                - sqPrev[prevBase + col];
    }

    asm volatile("cp.async.wait_group 1;" ::: "memory");
    __syncthreads();

    // A fragments (hi only): 16 regs, resident for whole kernel
    uint32_t afr[4][4];
    {
        const int arow = warp_r * 16 + (lane & 15);
        const uint32_t ab = sb + OFF_AH + (uint32_t)(arow * 128);
        const int aswz = arow & 7, achi = lane >> 4;
#pragma unroll
        for (int s = 0; s < 4; s++)
            ldsm4(afr[s], ab + (((2 * s + achi) ^ aswz) << 4));
    }

    const int b_row = (lane & 7) + ((lane >> 4) & 1) * 8;
    const int b_chi = (lane >> 3) & 1;
    const int bswz  = lane & 7;
    uint32_t bbase[4];
#pragma unroll
    for (int jp = 0; jp < 4; jp++)
        bbase[jp] = (uint32_t)((warp_c * 64 + jp * 16 + b_row) * 128);

    float acc[8][4];
#pragma unroll
    for (int j = 0; j < 8; j++)
#pragma unroll
        for (int q = 0; q < 4; q++) acc[j][q] = 0.f;

    float rmax[2];  rmax[0] = rmax[1] = -1e30f;
    int   cnt0 = 0, cnt1 = 0;

#pragma unroll 1
    for (int t = 0; t < 16; t++) {
        if (t < 15) asm volatile("cp.async.wait_group 1;" ::: "memory");
        else        asm volatile("cp.async.wait_group 0;" ::: "memory");
        __syncthreads();   // tile t visible; stage (t+2)%3 free

        if (t + 2 < 16) {
            const __nv_bfloat16* Bt = Bh_src + (size_t)(t + 2) * 128 * 64;
            uint32_t Bd = sb + (uint32_t)(((t + 2) % 3) * 16384);
#pragma unroll
            for (int j = 0; j < 4; j++) {
                int idx = tid + 256 * j;
                int row = idx >> 3, ch = idx & 7;
                cpasync16(Bd + (uint32_t)(row * 128 + ((ch ^ (row & 7)) << 4)),
                          Bt + (size_t)row * 64 + ch * 8);
            }
            CP_COMMIT();
        }

        const uint32_t sBuf = sb + (uint32_t)((t % 3) * 16384);

        // hi*hi screening GEMM: 4 k-steps x (4 LDSM + 8 MMA)
#pragma unroll
        for (int s = 0; s < 4; s++) {
            uint32_t bhi[4][4];
#pragma unroll
            for (int jp = 0; jp < 4; jp++)
                ldsm4(bhi[jp], sBuf + bbase[jp] + (((2 * s + b_chi) ^ bswz) << 4));
#pragma unroll
            for (int j = 0; j < 8; j++)
                mma16816(acc[j], afr[s], &bhi[j >> 1][(j & 1) * 2]);
        }

        // screening epilogue: p~ = 2*acc + c; collect candidates
        {
            const float* Ct = Cs + t * 128 + warp_c * 64 + 2 * (lane & 3);
            float cc[16];
#pragma unroll
            for (int j = 0; j < 8; j++) {
                cc[2*j]   = Ct[j * 8];
                cc[2*j+1] = Ct[j * 8 + 1];
            }
            const int colbase = t * 128 + warp_c * 64 + 2 * (lane & 3);
#pragma unroll
            for (int h = 0; h < 2; h++) {
                float p[16];
#pragma unroll
                for (int j = 0; j < 8; j++) {
                    p[2*j]   = fmaf(2.f, acc[j][2*h],     cc[2*j]);
                    p[2*j+1] = fmaf(2.f, acc[j][2*h + 1], cc[2*j+1]);
                }
                float tm = p[0];
#pragma unroll
                for (int j = 1; j < 16; j++) tm = fmaxf(tm, p[j]);
                if (tm > rmax[h] - MARGIN) {
                    float nm = fmaxf(tm, rmax[h]);
                    rmax[h] = nm;
                    float th = nm - MARGIN;
                    uint32_t* rg = ring + (tid * 2 + h) * 9;
                    int cn = h ? cnt1 : cnt0;
#pragma unroll
                    for (int j2 = 0; j2 < 16; j2++) {
                        if (p[j2] > th) {
                            uint32_t col = (uint32_t)(colbase + (j2 >> 1) * 8 + (j2 & 1));
                            uint32_t u = __float_as_uint(p[j2]);
                            uint32_t key = (u & 0x80000000u) ? ~u : (u | 0x80000000u);
                            uint32_t packed = (key & 0xFFFFF800u) | col;
                            if (cn < 8) {
                                rg[cn] = packed; cn++;
                            } else {
                                int mi = 0; uint32_t mv = rg[0];
#pragma unroll
                                for (int s2 = 1; s2 < 8; s2++)
                                    if (rg[s2] < mv) { mv = rg[s2]; mi = s2; }
                                if (packed > mv) rg[mi] = packed;
                            }
                        }
                    }
                    if (h) cnt1 = cn; else cnt0 = cn;
                }
            }
#pragma unroll
            for (int j = 0; j < 8; j++)
#pragma unroll
                for (int q = 0; q < 4; q++) acc[j][q] = 0.f;
        }
    }

    ring[(tid * 2 + 0) * 9 + 8] = (uint32_t)cnt0;
    ring[(tid * 2 + 1) * 9 + 8] = (uint32_t)cnt1;
    __syncthreads();

    // --- exact rescoring: 4 threads per row ---
    const int row = tid >> 2, ql = tid & 3;
    const int wr = row >> 4, hh = (row >> 3) & 1, qr = row & 7;
    const float4* Afrow = (const float4*)(smem + OFF_AF + row * 256);
    float M = -1e30f, S = 0.f;
#pragma unroll
    for (int wc = 0; wc < 2; wc++) {
        int tc = (wr * 2 + wc) * 32 + qr * 4 + ql;
        const uint32_t* rg = ring + (tc * 2 + hh) * 9;
        int cn = (int)rg[8];
        for (int s2 = 0; s2 < cn; s2++) {
            int col = (int)(rg[s2] & 0x7FFu);
            const float4* yv = (const float4*)(Bfp + (size_t)col * 64);
            float dot = 0.f;
#pragma unroll
            for (int k = 0; k < 16; k++) {
                float4 a = Afrow[k];
                float4 bq = __ldg(&yv[k]);
                dot += a.x * bq.x + a.y * bq.y + a.z * bq.z + a.w * bq.w;
            }
            float pe = fmaf(2.f, dot, Cs[col]);
            float nm = fmaxf(pe, M);
            S = S * __expf((M - nm) * IEPS) + __expf((pe - nm) * IEPS);
            M = nm;
        }
    }
    // merge the 4 lanes of this row
#pragma unroll
    for (int off = 1; off <= 2; off <<= 1) {
        float om = __shfl_xor_sync(0xffffffffu, M, off);
        float os = __shfl_xor_sync(0xffffffffu, S, off);
        float nm = fmaxf(M, om);
        S = S * __expf((M - nm) * IEPS) + os * __expf((om - nm) * IEPS);
        M = nm;
    }
    double contrib = 0.0;
    if (ql == 0) {
        int grow = r0 + row;
        float val = sqCur[curBase + grow] - M - EPSF * __logf(S);
        out[64 + (dir ? BTN : 0) + curBase + grow] = val;
        contrib = (double)__expf(loga[curBase + grow]) * (double)val;
    }
    dsm[tid] = contrib;
    __syncthreads();
    for (int s = 128; s > 0; s >>= 1) {
        if (tid < s) dsm[tid] += dsm[tid + s];
        __syncthreads();
    }
    if (tid == 0) g_lossPart[step & 1][bid] = dsm[0];

    // finish the PREVIOUS step's loss (written by the previous launch)
    if (bid == 0 && step > 1 && tid < 32) {
        double s = 0.0;
#pragma unroll
        for (int j = 0; j < 8; j++) s += g_lossPart[(step - 1) & 1][tid * 8 + j];
#pragma unroll
        for (int off = 16; off > 0; off >>= 1)
            s += __shfl_xor_sync(0xffffffffu, s, off);
        if (tid == 0) {
            float L = (float)s;
#pragma unroll
            for (int bq = 0; bq < BB; bq++) out[bq * TT + step - 1] = L;
        }
    }
}

// final step's loss
__global__ void loss_finish(float* __restrict__ out) {
    __shared__ double sm[128];
    int tid = threadIdx.x;
    sm[tid] = g_lossPart[(TT - 1) & 1][tid] + g_lossPart[(TT - 1) & 1][tid + 128];
    __syncthreads();
    for (int s = 64; s > 0; s >>= 1) {
        if (tid < s) sm[tid] += sm[tid + s];
        __syncthreads();
    }
    if (tid < 4) out[tid * TT + (TT - 1)] = (float)sm[0];
}

extern "C" void kernel_launch(void* const* d_in, const int* in_sizes, int n_in,
                              void* d_out, int out_size) {
    const float* x    = (const float*)d_in[0];
    const float* y    = (const float*)d_in[1];
    const float* loga = (const float*)d_in[2];
    const float* logb = (const float*)d_in[3];
    float* out = (float*)d_out;

    cudaFuncSetAttribute(main_kernel, cudaFuncAttributeMaxDynamicSharedMemorySize,
                         SMEM_TOT);

    split_kernel<<<16384, 256>>>(x, y);
    norms_kernel<<<1024, 256>>>(x, y);
    init_kernel<<<32, 256>>>(out);
    for (int step = 1; step < TT; step++) {
        main_kernel<<<256, 256, SMEM_TOT>>>(step, x, y, loga, logb, out);
    }
    loss_finish<<<1, 128>>>(out);
}

// round 17
// speedup vs baseline: 1.4681x; 1.4681x over previous
#include <cuda_runtime.h>
#include <cuda_bf16.h>
#include <math.h>
#include <stdint.h>

#define BB   4
#define TT   16
#define NN   2048
#define DD   64
#define EPSF 1e-4f
#define IEPS 1e4f
#define BTN  (BB*TT*NN)   // 131072 = 2^17
#define GMARG 0.35f

typedef unsigned long long u64;

// static device scratch (no allocations)
__device__ float  g_sqx[BTN];
__device__ float  g_sqy[BTN];
__device__ double g_lossPart[2][256];
// bf16 split storage: per row 128 bf16: [0:64]=hi, [64:128]=lo
__device__ __nv_bfloat16 g_xs[(size_t)BTN * 128];
__device__ __nv_bfloat16 g_ys[(size_t)BTN * 128];

__device__ __forceinline__ uint32_t smem_u32(const void* p) {
    uint32_t a;
    asm("{ .reg .u64 t; cvta.to.shared.u64 t, %1; cvt.u32.u64 %0, t; }"
        : "=r"(a) : "l"(p));
    return a;
}
__device__ __forceinline__ void ldsm4(uint32_t* r, uint32_t addr) {
    asm volatile("ldmatrix.sync.aligned.m8n8.x4.shared.b16 {%0,%1,%2,%3}, [%4];"
        : "=r"(r[0]), "=r"(r[1]), "=r"(r[2]), "=r"(r[3]) : "r"(addr));
}
__device__ __forceinline__ void mma16816(float* d, const uint32_t* a,
                                         const uint32_t* b) {
    asm volatile(
        "mma.sync.aligned.m16n8k16.row.col.f32.bf16.bf16.f32 "
        "{%0,%1,%2,%3}, {%4,%5,%6,%7}, {%8,%9}, {%0,%1,%2,%3};"
        : "+f"(d[0]), "+f"(d[1]), "+f"(d[2]), "+f"(d[3])
        : "r"(a[0]), "r"(a[1]), "r"(a[2]), "r"(a[3]), "r"(b[0]), "r"(b[1]));
}
__device__ __forceinline__ void cpasync16(uint32_t sm, const void* g) {
    asm volatile("cp.async.cg.shared.global [%0], [%1], 16;"
                 :: "r"(sm), "l"(g));
}
#define CP_COMMIT() asm volatile("cp.async.commit_group;" ::: "memory")

// ---------------- small kernels ----------------
__global__ void split_kernel(const float* __restrict__ x, const float* __restrict__ y) {
    int id = blockIdx.x * 256 + threadIdx.x;       // 0 .. 2*BTN*16-1
    int kind = id >> 21;                            // BTN*16 = 2^21
    int r = id & ((1 << 21) - 1);
    int row = r >> 4, c4 = (r & 15) << 2;
    const float* src = (kind ? y : x) + (size_t)row * DD + c4;
    float4 v = *(const float4*)src;
    union { __nv_bfloat16 h[4]; u64 v; } H, L;
    H.h[0] = __float2bfloat16(v.x); L.h[0] = __float2bfloat16(v.x - __bfloat162float(H.h[0]));
    H.h[1] = __float2bfloat16(v.y); L.h[1] = __float2bfloat16(v.y - __bfloat162float(H.h[1]));
    H.h[2] = __float2bfloat16(v.z); L.h[2] = __float2bfloat16(v.z - __bfloat162float(H.h[2]));
    H.h[3] = __float2bfloat16(v.w); L.h[3] = __float2bfloat16(v.w - __bfloat162float(H.h[3]));
    __nv_bfloat16* dst = (kind ? g_ys : g_xs) + (size_t)row * 128 + c4;
    *(u64*)dst = H.v;
    *(u64*)(dst + 64) = L.v;
}

__global__ void norms_kernel(const float* __restrict__ x, const float* __restrict__ y) {
    int id = blockIdx.x * 256 + threadIdx.x;
    int kind = id >> 17;
    int r = id & (BTN - 1);
    const float4* v = (const float4*)((kind ? y : x) + (size_t)r * DD);
    float s = 0.f;
#pragma unroll
    for (int k = 0; k < 16; k++) {
        float4 q = v[k];
        s += q.x * q.x + q.y * q.y + q.z * q.z + q.w * q.w;
    }
    (kind ? g_sqy : g_sqx)[r] = s;
}

__global__ void init_kernel(float* __restrict__ out) {
    int id = blockIdx.x * blockDim.x + threadIdx.x;   // 0..8191
    if (id < 4) out[id * TT] = 0.f;
    int b = id >> 11, i = id & 2047;
    out[64 + (b * TT) * NN + i] = 0.f;
    out[64 + BTN + (b * TT) * NN + i] = 0.f;
}

// ---------------- main mma.sync kernel (gated cross-terms) ----------------
// grid = 256: dir(2) x b(4) x rowblock(32). Block tile 64 rows x 2048 cols.
// 2 CTAs/SM. Warp tile 16x64; A fragments resident in registers.
// Per tile: hi*hi GEMM -> warp-uniform screen -> cross-term MMAs + exact
// epilogue only for tiles within GMARG of the running row max.
// SMEM: B ring stage0 0..32K | stage1 32K..64K | stage2 64K..96K (A staged
// here first) | Cs 96K..104K | comb 104K..105K | dsm 105K..107K
#define OFF_CS   98304
#define OFF_COMB 106496
#define OFF_DSM  107520
#define SMEM_TOT 109568

__global__ __launch_bounds__(256, 2)
void main_kernel(int step, const float* __restrict__ loga,
                 const float* __restrict__ logb, float* __restrict__ out) {
    extern __shared__ char smem[];
    const uint32_t sb = smem_u32(smem);
    float*  Cs   = (float*)(smem + OFF_CS);
    float*  comb = (float*)(smem + OFF_COMB);
    double* dsm  = (double*)(smem + OFF_DSM);

    const int tid = threadIdx.x;
    const int bid = blockIdx.x;
    const int dir = bid >> 7;
    const int b   = (bid >> 5) & 3;
    const int rb  = bid & 31;
    const int r0  = rb * 64;
    const int lane = tid & 31, wid = tid >> 5;
    const int warp_r = wid >> 1, warp_c = wid & 1;   // 4 x 2 warps, tile 16x64

    const size_t curBase  = (size_t)(b * TT + step) * NN;
    const size_t prevBase = curBase - NN;

    const __nv_bfloat16* Abase = (dir == 0 ? g_xs : g_ys) + (curBase + r0) * 128;
    const __nv_bfloat16* Bbase = (dir == 0 ? g_ys : g_xs) + prevBase * 128;
    const float* prevPot = out + 64 + (dir == 0 ? BTN : 0);
    const float* lvec    = (dir == 0 ? logb : loga);
    const float* sqPrev  = (dir == 0 ? g_sqy : g_sqx);
    const float* sqCur   = (dir == 0 ? g_sqx : g_sqy);

    const int ld_row0 = tid >> 4, ld_ch = tid & 15;

    // group 0: A tile (into ring stage 2) + B tile 0 (stage 0)
#pragma unroll
    for (int j = 0; j < 4; j++) {
        int row = ld_row0 + 16 * j;
        cpasync16(sb + 65536 + (uint32_t)(row * 256 + ((ld_ch ^ (row & 7)) << 4)),
                  Abase + (size_t)row * 128 + ld_ch * 8);
    }
#pragma unroll
    for (int j = 0; j < 8; j++) {
        int row = ld_row0 + 16 * j;
        cpasync16(sb + (uint32_t)(row * 256 + ((ld_ch ^ (row & 7)) << 4)),
                  Bbase + (size_t)row * 128 + ld_ch * 8);
    }
    CP_COMMIT();
    // group 1: B tile 1 (stage 1)
#pragma unroll
    for (int j = 0; j < 8; j++) {
        int row = ld_row0 + 16 * j;
        cpasync16(sb + 32768 + (uint32_t)(row * 256 + ((ld_ch ^ (row & 7)) << 4)),
                  Bbase + (size_t)(128 + row) * 128 + ld_ch * 8);
    }
    CP_COMMIT();
    // c vector
#pragma unroll
    for (int j = 0; j < 8; j++) {
        int col = tid + 256 * j;
        Cs[col] = prevPot[prevBase + col] + EPSF * lvec[prevBase + col]
                - sqPrev[prevBase + col];
    }

    // wait A (+B0), extract A fragments once for the whole kernel
    asm volatile("cp.async.wait_group 1;" ::: "memory");
    __syncthreads();

    uint32_t afr[2][4][4];   // [hilo][kstep][4] — 32 regs, resident
    {
        const int arow = warp_r * 16 + (lane & 15);
        const uint32_t ab = sb + 65536 + (uint32_t)(arow * 256);
        const int aswz = arow & 7, achi = lane >> 4;
#pragma unroll
        for (int hl = 0; hl < 2; hl++)
#pragma unroll
            for (int s = 0; s < 4; s++)
                ldsm4(afr[hl][s], ab + (((hl * 8 + 2 * s + achi) ^ aswz) << 4));
    }
    __syncthreads();   // all warps done reading A from stage 2

    const int b_row = (lane & 7) + ((lane >> 4) & 1) * 8;
    const int b_chi = (lane >> 3) & 1;
    const int bswz  = lane & 7;
    uint32_t bbase[4];
#pragma unroll
    for (int jp = 0; jp < 4; jp++)
        bbase[jp] = (uint32_t)((warp_c * 64 + jp * 16 + b_row) * 256);

    float acc[8][4];
#pragma unroll
    for (int j = 0; j < 8; j++)
#pragma unroll
        for (int q = 0; q < 4; q++) acc[j][q] = 0.f;

    float rmax[2], rsum[2], rmaxS[2];
    rmax[0] = rmax[1] = -INFINITY; rsum[0] = rsum[1] = 0.f;
    rmaxS[0] = rmaxS[1] = -1e30f;

#pragma unroll 1
    for (int t = 0; t < 16; t++) {
        if (t < 15) asm volatile("cp.async.wait_group 1;" ::: "memory");
        else        asm volatile("cp.async.wait_group 0;" ::: "memory");
        __syncthreads();   // tile t visible; stage (t+2)%3 free

        if (t + 2 < 16) {
            const __nv_bfloat16* Bt = Bbase + (size_t)(t + 2) * 128 * 128;
            uint32_t Bd = sb + (uint32_t)(((t + 2) % 3) * 32768);
#pragma unroll
            for (int j = 0; j < 8; j++) {
                int row = ld_row0 + 16 * j;
                cpasync16(Bd + (uint32_t)(row * 256 + ((ld_ch ^ (row & 7)) << 4)),
                          Bt + (size_t)row * 128 + ld_ch * 8);
            }
            CP_COMMIT();
        }

        const uint32_t sBuf = sb + (uint32_t)((t % 3) * 32768);

        // phase 1: hi*hi screening GEMM (4 LDSM + 8 MMA per k-step)
#pragma unroll
        for (int s = 0; s < 4; s++) {
            uint32_t bhi[4][4];
#pragma unroll
            for (int jp = 0; jp < 4; jp++)
                ldsm4(bhi[jp], sBuf + bbase[jp] + (((2 * s + b_chi) ^ bswz) << 4));
#pragma unroll
            for (int j = 0; j < 8; j++)
                mma16816(acc[j], afr[0][s], &bhi[j >> 1][(j & 1) * 2]);
        }

        // screen: tile-max of p~ per row-half, warp-uniform gate
        const float* Ct = Cs + t * 128 + warp_c * 64 + 2 * (lane & 3);
        float cc[16];
#pragma unroll
        for (int j = 0; j < 8; j++) {
            cc[2*j]   = Ct[j * 8];
            cc[2*j+1] = Ct[j * 8 + 1];
        }
        float tms[2];
#pragma unroll
        for (int h = 0; h < 2; h++) {
            float tm = -1e30f;
#pragma unroll
            for (int j = 0; j < 8; j++) {
                tm = fmaxf(tm, fmaf(2.f, acc[j][2*h],     cc[2*j]));
                tm = fmaxf(tm, fmaf(2.f, acc[j][2*h + 1], cc[2*j+1]));
            }
            tms[h] = tm;
        }
        bool pass = (tms[0] > rmaxS[0] - GMARG) || (tms[1] > rmaxS[1] - GMARG);
        rmaxS[0] = fmaxf(rmaxS[0], tms[0]);
        rmaxS[1] = fmaxf(rmaxS[1], tms[1]);

        if (__ballot_sync(0xffffffffu, pass)) {
            // phase 2: cross terms (lo*hi + hi*lo)
#pragma unroll
            for (int s = 0; s < 4; s++) {
                uint32_t bf2[4][4];
#pragma unroll
                for (int jp = 0; jp < 4; jp++)
                    ldsm4(bf2[jp], sBuf + bbase[jp] + (((2 * s + b_chi) ^ bswz) << 4));
#pragma unroll
                for (int j = 0; j < 8; j++)
                    mma16816(acc[j], afr[1][s], &bf2[j >> 1][(j & 1) * 2]);
#pragma unroll
                for (int jp = 0; jp < 4; jp++)
                    ldsm4(bf2[jp], sBuf + bbase[jp] + (((8 + 2 * s + b_chi) ^ bswz) << 4));
#pragma unroll
                for (int j = 0; j < 8; j++)
                    mma16816(acc[j], afr[0][s], &bf2[j >> 1][(j & 1) * 2]);
            }
            // exact epilogue on full-precision acc
#pragma unroll
            for (int h = 0; h < 2; h++) {
                float p[16];
#pragma unroll
                for (int j = 0; j < 8; j++) {
                    p[2*j]   = fmaf(2.f, acc[j][2*h],     cc[2*j]);
                    p[2*j+1] = fmaf(2.f, acc[j][2*h + 1], cc[2*j+1]);
                }
                float tm = p[0];
#pragma unroll
                for (int j = 1; j < 16; j++) tm = fmaxf(tm, p[j]);
                if (tm > rmax[h] - 0.0090f) {   // else all exps underflow to 0
                    float nm = fmaxf(tm, rmax[h]);
                    float s2 = 0.f;
#pragma unroll
                    for (int j = 0; j < 16; j++)
                        s2 += __expf((p[j] - nm) * IEPS);
                    rsum[h] = rsum[h] * __expf((rmax[h] - nm) * IEPS) + s2;
                    rmax[h] = nm;
                }
            }
        }
#pragma unroll
        for (int j = 0; j < 8; j++)
#pragma unroll
            for (int q = 0; q < 4; q++) acc[j][q] = 0.f;
    }

    // in-warp combine over the 4 lanes sharing a row
#pragma unroll
    for (int h = 0; h < 2; h++) {
        float m = rmax[h], s = rsum[h];
#pragma unroll
        for (int off = 1; off <= 2; off <<= 1) {
            float om = __shfl_xor_sync(0xffffffffu, m, off);
            float os = __shfl_xor_sync(0xffffffffu, s, off);
            float nm = fmaxf(m, om);
            s = s * __expf((m - nm) * IEPS) + os * __expf((om - nm) * IEPS);
            m = nm;
        }
        if ((lane & 3) == 0) {
            int rl = warp_r * 16 + h * 8 + (lane >> 2);
            comb[(rl * 2 + warp_c) * 2]     = m;
            comb[(rl * 2 + warp_c) * 2 + 1] = s;
        }
    }
    __syncthreads();

    double contrib = 0.0;
    if (tid < 64) {
        float m0 = comb[tid * 4],     s0 = comb[tid * 4 + 1];
        float m1 = comb[tid * 4 + 2], s1 = comb[tid * 4 + 3];
        float M = fmaxf(m0, m1);
        float S = s0 * __expf((m0 - M) * IEPS) + s1 * __expf((m1 - M) * IEPS);
        int row = r0 + tid;
        float val = sqCur[curBase + row] - M - EPSF * __logf(S);
        out[64 + (dir ? BTN : 0) + curBase + row] = val;
        contrib = (double)__expf(loga[curBase + row]) * (double)val;
    }
    dsm[tid] = contrib;
    __syncthreads();
    for (int s = 128; s > 0; s >>= 1) {
        if (tid < s) dsm[tid] += dsm[tid + s];
        __syncthreads();
    }
    if (tid == 0) g_lossPart[step & 1][bid] = dsm[0];

    // finish the PREVIOUS step's loss (written by the previous launch)
    if (bid == 0 && step > 1 && tid < 32) {
        double s = 0.0;
#pragma unroll
        for (int j = 0; j < 8; j++) s += g_lossPart[(step - 1) & 1][tid * 8 + j];
#pragma unroll
        for (int off = 16; off > 0; off >>= 1)
            s += __shfl_xor_sync(0xffffffffu, s, off);
        if (tid == 0) {
            float L = (float)s;
#pragma unroll
            for (int bq = 0; bq < BB; bq++) out[bq * TT + step - 1] = L;
        }
    }
}

// final step's loss
__global__ void loss_finish(float* __restrict__ out) {
    __shared__ double sm[128];
    int tid = threadIdx.x;
    sm[tid] = g_lossPart[(TT - 1) & 1][tid] + g_lossPart[(TT - 1) & 1][tid + 128];
    __syncthreads();
    for (int s = 64; s > 0; s >>= 1) {
        if (tid < s) sm[tid] += sm[tid + s];
        __syncthreads();
    }
    if (tid < 4) out[tid * TT + (TT - 1)] = (float)sm[0];
}

extern "C" void kernel_launch(void* const* d_in, const int* in_sizes, int n_in,
                              void* d_out, int out_size) {
    const float* x    = (const float*)d_in[0];
    const float* y    = (const float*)d_in[1];
    const float* loga = (const float*)d_in[2];
    const float* logb = (const float*)d_in[3];
    float* out = (float*)d_out;

    cudaFuncSetAttribute(main_kernel, cudaFuncAttributeMaxDynamicSharedMemorySize,
                         SMEM_TOT);

    split_kernel<<<16384, 256>>>(x, y);
    norms_kernel<<<1024, 256>>>(x, y);
    init_kernel<<<32, 256>>>(out);
    for (int step = 1; step < TT; step++) {
        main_kernel<<<256, 256, SMEM_TOT>>>(step, loga, logb, out);
    }
    loss_finish<<<1, 128>>>(out);
}